// round 15
// baseline (speedup 1.0000x reference)
#include <cuda_runtime.h>
#include <cuda_bf16.h>
#include <mma.h>
#include <cstdint>

using namespace nvcuda;
typedef __nv_bfloat16 bf16;

#define BB    8
#define SEQ   1024
#define CDIM  1024
#define NHEAD 16
#define HD    64
#define HID   4096
#define MTOK  (BB*SEQ)           // 8192
#define NOUT1 (HID + 3*CDIM)     // 7168
#define KCAT  (HID + CDIM)       // 5120

// ------------------------- scratch (static device globals) ------------------
__device__ bf16  g_y  [(size_t)MTOK*CDIM];     // LN(x) in bf16
__device__ bf16  g_W1 [(size_t)NOUT1*CDIM];    // in_proj_w bf16
__device__ bf16  g_W2 [(size_t)CDIM*KCAT];     // folded out_proj_w bf16
__device__ float g_b2 [CDIM];                  // folded out_proj_b
__device__ bf16  g_cat[(size_t)MTOK*KCAT];     // [gelu(mlp) | x_attn]
__device__ bf16  g_Q  [(size_t)MTOK*CDIM];     // [B,H,N,D]
__device__ bf16  g_K  [(size_t)MTOK*CDIM];
__device__ bf16  g_V  [(size_t)MTOK*CDIM];

// ------------------------- weight conversion kernels ------------------------
__global__ void k_convw1(const float* __restrict__ w){
    size_t idx = ((size_t)blockIdx.x*blockDim.x + threadIdx.x)*4;
    float4 v = *(const float4*)(w + idx);
    bf16 t[4] = {__float2bfloat16(v.x), __float2bfloat16(v.y),
                 __float2bfloat16(v.z), __float2bfloat16(v.w)};
    *(uint2*)&g_W1[idx] = *(uint2*)t;
}

__global__ void k_convw2(const float* __restrict__ w){
    size_t idx = ((size_t)blockIdx.x*blockDim.x + threadIdx.x)*4;
    float4 a = *(const float4*)(w + idx);
    float4 b = *(const float4*)(w + (size_t)CDIM*KCAT + idx);
    bf16 t[4] = {__float2bfloat16(a.x+b.x), __float2bfloat16(a.y+b.y),
                 __float2bfloat16(a.z+b.z), __float2bfloat16(a.w+b.w)};
    *(uint2*)&g_W2[idx] = *(uint2*)t;
}

__global__ void k_b2(const float* __restrict__ ob){
    int c = blockIdx.x*blockDim.x + threadIdx.x;
    if (c < CDIM) g_b2[c] = ob[c] + ob[CDIM + c];
}

// ------------------------- LN over C=1024 (input) ----------------------------
__global__ void k_ln1(const float* __restrict__ x,
                      const float* __restrict__ w,
                      const float* __restrict__ b){
    int row = blockIdx.x;
    int tid = threadIdx.x;
    const float* xr = x + (size_t)row*CDIM;
    float4 v = ((const float4*)xr)[tid];
    float s  = v.x + v.y + v.z + v.w;
    float sq = v.x*v.x + v.y*v.y + v.z*v.z + v.w*v.w;
    #pragma unroll
    for (int o = 16; o; o >>= 1){
        s  += __shfl_xor_sync(0xffffffffu, s,  o);
        sq += __shfl_xor_sync(0xffffffffu, sq, o);
    }
    __shared__ float ss[8], ssq[8];
    __shared__ float smean, srstd;
    int wp = tid >> 5, ln = tid & 31;
    if (ln == 0){ ss[wp] = s; ssq[wp] = sq; }
    __syncthreads();
    if (tid == 0){
        float S = 0.f, Q = 0.f;
        #pragma unroll
        for (int i = 0; i < 8; i++){ S += ss[i]; Q += ssq[i]; }
        float mean = S * (1.f/CDIM);
        float var  = Q * (1.f/CDIM) - mean*mean;
        smean = mean; srstd = rsqrtf(var + 1e-5f);
    }
    __syncthreads();
    float mean = smean, rs = srstd;
    float4 wv = ((const float4*)w)[tid];
    float4 bv = ((const float4*)b)[tid];
    bf16 t[4];
    t[0] = __float2bfloat16((v.x-mean)*rs*wv.x + bv.x);
    t[1] = __float2bfloat16((v.y-mean)*rs*wv.y + bv.y);
    t[2] = __float2bfloat16((v.z-mean)*rs*wv.z + bv.z);
    t[3] = __float2bfloat16((v.w-mean)*rs*wv.w + bv.w);
    *(uint2*)&g_y[(size_t)row*CDIM + tid*4] = *(uint2*)t;
}

// ------------------------- q/k per-head LN over D=64 ------------------------
__global__ void k_qkln(const float* __restrict__ qw, const float* __restrict__ qb,
                       const float* __restrict__ kw, const float* __restrict__ kb){
    int gwarp = (blockIdx.x*blockDim.x + threadIdx.x) >> 5;
    int lane  = threadIdx.x & 31;
    const int ROWS = BB*NHEAD*SEQ;
    int tensor = (gwarp >= ROWS) ? 1 : 0;
    int row    = tensor ? gwarp - ROWS : gwarp;
    bf16* buf  = tensor ? g_K : g_Q;
    const float* w = tensor ? kw : qw;
    const float* b = tensor ? kb : qb;
    bf16* p = buf + (size_t)row*HD;
    float x0 = __bfloat162float(p[lane]);
    float x1 = __bfloat162float(p[lane+32]);
    float s  = x0 + x1;
    float sq = x0*x0 + x1*x1;
    #pragma unroll
    for (int o = 16; o; o >>= 1){
        s  += __shfl_xor_sync(0xffffffffu, s,  o);
        sq += __shfl_xor_sync(0xffffffffu, sq, o);
    }
    float mean = s * (1.f/HD);
    float var  = sq * (1.f/HD) - mean*mean;
    float rs   = rsqrtf(var + 1e-5f);
    p[lane]    = __float2bfloat16((x0-mean)*rs*w[lane]    + b[lane]);
    p[lane+32] = __float2bfloat16((x1-mean)*rs*w[lane+32] + b[lane+32]);
}

// ------------------------- bf16 NT GEMM (wmma, 128x256, BK=64) --------------
#define BM 128
#define BN 256
#define BK 64
#define LDS 72                      // halves stride per smem row (64 data + 8 pad)
#define LDC 260                     // floats stride for epilogue staging
#define GEMM_SMEM (BM*LDC*4)        // 133120 > 2*(BM+BN)*LDS*2 = 110592

__device__ __forceinline__ void cp16(void* s, const void* g){
    unsigned int a = (unsigned int)__cvta_generic_to_shared(s);
    asm volatile("cp.async.cg.shared.global [%0], [%1], 16;\n" :: "r"(a), "l"(g));
}

// EPI==1: A=g_y, B=g_W1, K=1024; epilogue = bias + gelu / scatter q,k,v (p0=mlp_bias)
// EPI==2: A=g_cat, B=g_W2, K=5120; epilogue = x + ls_gamma*(acc + b2) (p0=x, p1=lsg)
template<int EPI, int KD>
__global__ void __launch_bounds__(256) k_gemm(const float* __restrict__ p0,
                                              const float* __restrict__ p1,
                                              float* __restrict__ pout){
    extern __shared__ char smem[];
    bf16*  sA = (bf16*)smem;                    // 2 stages x BM x LDS
    bf16*  sB = sA + 2*BM*LDS;                  // 2 stages x BN x LDS
    float* sC = (float*)smem;                   // epilogue overlay
    const bf16* A = (EPI == 1) ? g_y  : g_cat;
    const bf16* B = (EPI == 1) ? g_W1 : g_W2;
    int bx = blockIdx.x, by = blockIdx.y;
    int tid = threadIdx.x;
    const bf16* Ab = A + (size_t)by*BM*KD;
    const bf16* Bb = B + (size_t)bx*BN*KD;

    wmma::fragment<wmma::accumulator,16,16,16,float> acc[4][4];
    #pragma unroll
    for (int i = 0; i < 4; i++)
        #pragma unroll
        for (int j = 0; j < 4; j++) wmma::fill_fragment(acc[i][j], 0.f);

    int warp = tid >> 5, wm = warp >> 2, wn = warp & 3;   // 2 x 4 warps, 64x64 tiles
    const int KT = KD / BK;

    auto load_stage = [&](int st, int kt){
        int k0 = kt*BK;
        // A: 128 rows x 8 segs of 16B (=8 halves); 1024 chunks / 256 thr = 4
        #pragma unroll
        for (int i = 0; i < 4; i++){
            int ch = tid + i*256;
            int r = ch >> 3, s8 = (ch & 7) * 8;
            cp16(&sA[(size_t)st*BM*LDS + r*LDS + s8], Ab + (size_t)r*KD + k0 + s8);
        }
        // B: 256 rows x 8 segs; 2048 chunks / 256 thr = 8
        #pragma unroll
        for (int i = 0; i < 8; i++){
            int ch = tid + i*256;
            int r = ch >> 3, s8 = (ch & 7) * 8;
            cp16(&sB[(size_t)st*BN*LDS + r*LDS + s8], Bb + (size_t)r*KD + k0 + s8);
        }
        asm volatile("cp.async.commit_group;\n");
    };

    load_stage(0, 0);
    for (int kt = 0; kt < KT; kt++){
        if (kt + 1 < KT){
            load_stage((kt+1) & 1, kt+1);
            asm volatile("cp.async.wait_group 1;\n");
        } else {
            asm volatile("cp.async.wait_group 0;\n");
        }
        __syncthreads();
        const bf16* pA = &sA[(size_t)(kt & 1)*BM*LDS];
        const bf16* pB = &sB[(size_t)(kt & 1)*BN*LDS];
        #pragma unroll
        for (int kk = 0; kk < BK; kk += 16){
            wmma::fragment<wmma::matrix_a,16,16,16,bf16,wmma::row_major> a[4];
            #pragma unroll
            for (int i = 0; i < 4; i++)
                wmma::load_matrix_sync(a[i], pA + (wm*64 + i*16)*LDS + kk, LDS);
            #pragma unroll
            for (int j = 0; j < 4; j++){
                wmma::fragment<wmma::matrix_b,16,16,16,bf16,wmma::col_major> bfr;
                wmma::load_matrix_sync(bfr, pB + (wn*64 + j*16)*LDS + kk, LDS);
                #pragma unroll
                for (int i = 0; i < 4; i++)
                    wmma::mma_sync(acc[i][j], a[i], bfr, acc[i][j]);
            }
        }
        __syncthreads();
    }

    // epilogue: stage accumulators in shared, then transform per element
    #pragma unroll
    for (int i = 0; i < 4; i++)
        #pragma unroll
        for (int j = 0; j < 4; j++)
            wmma::store_matrix_sync(&sC[(wm*64 + i*16)*LDC + wn*64 + j*16],
                                    acc[i][j], LDC, wmma::mem_row_major);
    __syncthreads();

    // 128 rows x 256 cols; thread tid handles column tid of row e (coalesced)
    #pragma unroll 2
    for (int e = 0; e < BM; e++){
        int r = e, c = tid;
        float v = sC[r*LDC + c];
        int m = by*BM + r;              // token
        int o = bx*BN + c;              // output feature
        if (EPI == 1){
            // reference bias layout: bias = concat(zeros(3C), mlp_bias)
            if (o >= 3*CDIM) v += p0[o - 3*CDIM];
            if (o < HID){
                float g = 0.5f * v * (1.f + erff(v * 0.70710678118654752f));
                g_cat[(size_t)m*KCAT + o] = __float2bfloat16(g);
            } else {
                int c2 = o - HID;
                int reg = c2 >> 10;     // 0=q, 1=k, 2=v
                int cc  = c2 & 1023;
                int h = cc >> 6, d = cc & 63;
                int b = m >> 10, n = m & 1023;
                size_t off = ((size_t)(b*NHEAD + h)*SEQ + n)*HD + d;
                bf16 val = __float2bfloat16(v);
                if (reg == 0)      g_Q[off] = val;
                else if (reg == 1) g_K[off] = val;
                else               g_V[off] = val;
            }
        } else {
            size_t oi = (size_t)m*CDIM + o;
            pout[oi] = p0[oi] + p1[o] * (v + g_b2[o]);   // x + ls_gamma*(...)
        }
    }
}

// ------------------------- flash attention (64x64 tiles) --------------------
#define LQK 72
#define LSF 68
#define ATTN_SMEM (4*64*LQK*2 + 2*64*LSF*4 + 3*64*4)   // 72448

__global__ void __launch_bounds__(128) k_attn(){
    extern __shared__ char sm_[];
    bf16*  sQ = (bf16*)sm_;
    bf16*  sK = sQ + 64*LQK;
    bf16*  sV = sK + 64*LQK;
    bf16*  sP = sV + 64*LQK;
    float* sS = (float*)(sP + 64*LQK);
    float* sO = sS + 64*LSF;
    float* sM = sO + 64*LSF;
    float* sL = sM + 64;
    float* sAl = sL + 64;

    int bid = blockIdx.x;
    int qt = bid & 15, bh = bid >> 4;
    int tid = threadIdx.x;
    const bf16* Qb = g_Q + (size_t)bh*SEQ*HD;
    const bf16* Kb = g_K + (size_t)bh*SEQ*HD;
    const bf16* Vb = g_V + (size_t)bh*SEQ*HD;

    #pragma unroll
    for (int i = 0; i < 4; i++){
        int ch = tid + i*128;
        int r = ch >> 3, c8 = (ch & 7) * 8;
        *(float4*)&sQ[r*LQK + c8] = *(const float4*)&Qb[(size_t)(qt*64 + r)*HD + c8];
    }
    for (int i = tid; i < 64*LSF; i += 128) sO[i] = 0.f;
    if (tid < 64){ sM[tid] = -1e30f; sL[tid] = 0.f; }
    __syncthreads();

    int w = tid >> 5;
    for (int j = 0; j < 16; j++){
        #pragma unroll
        for (int i = 0; i < 4; i++){
            int ch = tid + i*128;
            int r = ch >> 3, c8 = (ch & 7) * 8;
            *(float4*)&sK[r*LQK + c8] = *(const float4*)&Kb[(size_t)(j*64 + r)*HD + c8];
            *(float4*)&sV[r*LQK + c8] = *(const float4*)&Vb[(size_t)(j*64 + r)*HD + c8];
        }
        __syncthreads();

        { // S = scale * Q @ K^T
            wmma::fragment<wmma::accumulator,16,16,16,float> s[4];
            #pragma unroll
            for (int n = 0; n < 4; n++) wmma::fill_fragment(s[n], 0.f);
            #pragma unroll
            for (int kk = 0; kk < 64; kk += 16){
                wmma::fragment<wmma::matrix_a,16,16,16,bf16,wmma::row_major> a;
                wmma::load_matrix_sync(a, sQ + (w*16)*LQK + kk, LQK);
                #pragma unroll
                for (int n = 0; n < 4; n++){
                    wmma::fragment<wmma::matrix_b,16,16,16,bf16,wmma::col_major> bfr;
                    wmma::load_matrix_sync(bfr, sK + (n*16)*LQK + kk, LQK);
                    wmma::mma_sync(s[n], a, bfr, s[n]);
                }
            }
            #pragma unroll
            for (int n = 0; n < 4; n++){
                #pragma unroll
                for (int e = 0; e < s[n].num_elements; e++) s[n].x[e] *= 0.125f;
                wmma::store_matrix_sync(sS + (w*16)*LSF + n*16, s[n], LSF, wmma::mem_row_major);
            }
        }
        __syncthreads();

        if (tid < 64){  // online softmax row update
            float* sr = sS + tid*LSF;
            float mold = sM[tid];
            float ml = -1e30f;
            #pragma unroll 8
            for (int c = 0; c < 64; c++) ml = fmaxf(ml, sr[c]);
            float mnew  = fmaxf(mold, ml);
            float alpha = __expf(mold - mnew);
            float sum = 0.f;
            bf16* pr = sP + tid*LQK;
            #pragma unroll 8
            for (int c = 0; c < 64; c++){
                float p = __expf(sr[c] - mnew);
                sum += p;
                pr[c] = __float2bfloat16(p);
            }
            sM[tid] = mnew;
            sL[tid] = sL[tid]*alpha + sum;
            sAl[tid] = alpha;
        }
        __syncthreads();

        for (int i = tid; i < 64*64; i += 128){
            int r = i >> 6, c = i & 63;
            sO[r*LSF + c] *= sAl[r];
        }
        __syncthreads();

        { // O += P @ V
            wmma::fragment<wmma::matrix_a,16,16,16,bf16,wmma::row_major> a[4];
            #pragma unroll
            for (int kk = 0; kk < 4; kk++)
                wmma::load_matrix_sync(a[kk], sP + (w*16)*LQK + kk*16, LQK);
            #pragma unroll
            for (int n = 0; n < 4; n++){
                wmma::fragment<wmma::accumulator,16,16,16,float> cf;
                wmma::load_matrix_sync(cf, sO + (w*16)*LSF + n*16, LSF, wmma::mem_row_major);
                #pragma unroll
                for (int kk = 0; kk < 4; kk++){
                    wmma::fragment<wmma::matrix_b,16,16,16,bf16,wmma::row_major> bfr;
                    wmma::load_matrix_sync(bfr, sV + (kk*16)*LQK + n*16, LQK);
                    wmma::mma_sync(cf, a[kk], bfr, cf);
                }
                wmma::store_matrix_sync(sO + (w*16)*LSF + n*16, cf, LSF, wmma::mem_row_major);
            }
        }
        __syncthreads();
    }

    if (tid < 64){
        float inv = 1.f / sL[tid];
        int b = bh >> 4, h = bh & 15;
        int n = qt*64 + tid;
        bf16* dst = g_cat + (size_t)(b*SEQ + n)*KCAT + HID + h*64;
        #pragma unroll 8
        for (int c = 0; c < 64; c++)
            dst[c] = __float2bfloat16(sO[tid*LSF + c] * inv);
    }
}

// ------------------------- launch --------------------------------------------
extern "C" void kernel_launch(void* const* d_in, const int* in_sizes, int n_in,
                              void* d_out, int out_size){
    (void)in_sizes; (void)n_in; (void)out_size;
    const float* x     = (const float*)d_in[0];
    const float* inw   = (const float*)d_in[1];
    const float* inb   = (const float*)d_in[2];
    const float* w1    = (const float*)d_in[3];
    const float* mbias = (const float*)d_in[4];
    const float* qw    = (const float*)d_in[5];
    const float* qb    = (const float*)d_in[6];
    const float* kw    = (const float*)d_in[7];
    const float* kb    = (const float*)d_in[8];
    const float* w2    = (const float*)d_in[9];
    const float* ob    = (const float*)d_in[10];
    const float* lsg   = (const float*)d_in[11];
    float* out = (float*)d_out;

    cudaFuncSetAttribute(k_gemm<1, CDIM>, cudaFuncAttributeMaxDynamicSharedMemorySize, GEMM_SMEM);
    cudaFuncSetAttribute(k_gemm<2, KCAT>, cudaFuncAttributeMaxDynamicSharedMemorySize, GEMM_SMEM);
    cudaFuncSetAttribute(k_attn,          cudaFuncAttributeMaxDynamicSharedMemorySize, ATTN_SMEM);

    k_convw1<<<(NOUT1*CDIM/4)/256, 256>>>(w1);
    k_convw2<<<(CDIM*KCAT/4)/256, 256>>>(w2);
    k_b2<<<4, 256>>>(ob);
    k_ln1<<<MTOK, 256>>>(x, inw, inb);

    dim3 g1(NOUT1/BN, MTOK/BM);            // (28, 64)
    k_gemm<1, CDIM><<<g1, 256, GEMM_SMEM>>>(mbias, nullptr, nullptr);

    k_qkln<<<(2*BB*NHEAD*SEQ)/8, 256>>>(qw, qb, kw, kb);

    k_attn<<<BB*NHEAD*(SEQ/64), 128, ATTN_SMEM>>>();

    dim3 g2(CDIM/BN, MTOK/BM);             // (4, 64)
    k_gemm<2, KCAT><<<g2, 256, GEMM_SMEM>>>(x, lsg, out);
}

// round 16
// speedup vs baseline: 1.0775x; 1.0775x over previous
#include <cuda_runtime.h>
#include <cuda_bf16.h>
#include <cuda_fp8.h>
#include <mma.h>
#include <cstdint>

using namespace nvcuda;
typedef __nv_bfloat16 bf16;

#define BB    8
#define SEQ   1024
#define CDIM  1024
#define NHEAD 16
#define HD    64
#define HID   4096
#define MTOK  (BB*SEQ)           // 8192
#define NOUT1 (HID + 3*CDIM)     // 7168
#define KCAT  (HID + CDIM)       // 5120

// ------------------------- scratch (static device globals) ------------------
__device__ uint8_t g_yf8 [(size_t)MTOK*CDIM];    // LN(x) e4m3
__device__ uint8_t g_W1f8[(size_t)NOUT1*CDIM];   // in_proj_w e4m3
__device__ uint8_t g_W2f8[(size_t)CDIM*KCAT];    // folded out_proj_w e4m3
__device__ float   g_b2  [CDIM];                 // folded out_proj_b
__device__ uint8_t g_catf8[(size_t)MTOK*KCAT];   // [gelu(mlp) | x_attn] e4m3
__device__ bf16    g_Q  [(size_t)MTOK*CDIM];     // [B,H,N,D] bf16
__device__ bf16    g_K  [(size_t)MTOK*CDIM];
__device__ bf16    g_V  [(size_t)MTOK*CDIM];

__device__ __forceinline__ uint8_t f2e4m3(float f){
    return (uint8_t)__nv_cvt_float_to_fp8(f, __NV_SATFINITE, __NV_E4M3);
}
__device__ __forceinline__ uint32_t pack4_e4m3(float a, float b, float c, float d){
    return (uint32_t)f2e4m3(a) | ((uint32_t)f2e4m3(b) << 8) |
           ((uint32_t)f2e4m3(c) << 16) | ((uint32_t)f2e4m3(d) << 24);
}

// ------------------------- weight conversion kernels ------------------------
__global__ void k_convw1(const float* __restrict__ w){
    size_t idx = ((size_t)blockIdx.x*blockDim.x + threadIdx.x)*4;
    float4 v = *(const float4*)(w + idx);
    *(uint32_t*)&g_W1f8[idx] = pack4_e4m3(v.x, v.y, v.z, v.w);
}

__global__ void k_convw2(const float* __restrict__ w){
    size_t idx = ((size_t)blockIdx.x*blockDim.x + threadIdx.x)*4;
    float4 a = *(const float4*)(w + idx);
    float4 b = *(const float4*)(w + (size_t)CDIM*KCAT + idx);
    *(uint32_t*)&g_W2f8[idx] = pack4_e4m3(a.x+b.x, a.y+b.y, a.z+b.z, a.w+b.w);
}

__global__ void k_b2(const float* __restrict__ ob){
    int c = blockIdx.x*blockDim.x + threadIdx.x;
    if (c < CDIM) g_b2[c] = ob[c] + ob[CDIM + c];
}

// ------------------------- LN over C=1024 (input) ----------------------------
__global__ void k_ln1(const float* __restrict__ x,
                      const float* __restrict__ w,
                      const float* __restrict__ b){
    int row = blockIdx.x;
    int tid = threadIdx.x;
    const float* xr = x + (size_t)row*CDIM;
    float4 v = ((const float4*)xr)[tid];
    float s  = v.x + v.y + v.z + v.w;
    float sq = v.x*v.x + v.y*v.y + v.z*v.z + v.w*v.w;
    #pragma unroll
    for (int o = 16; o; o >>= 1){
        s  += __shfl_xor_sync(0xffffffffu, s,  o);
        sq += __shfl_xor_sync(0xffffffffu, sq, o);
    }
    __shared__ float ss[8], ssq[8];
    __shared__ float smean, srstd;
    int wp = tid >> 5, ln = tid & 31;
    if (ln == 0){ ss[wp] = s; ssq[wp] = sq; }
    __syncthreads();
    if (tid == 0){
        float S = 0.f, Q = 0.f;
        #pragma unroll
        for (int i = 0; i < 8; i++){ S += ss[i]; Q += ssq[i]; }
        float mean = S * (1.f/CDIM);
        float var  = Q * (1.f/CDIM) - mean*mean;
        smean = mean; srstd = rsqrtf(var + 1e-5f);
    }
    __syncthreads();
    float mean = smean, rs = srstd;
    float4 wv = ((const float4*)w)[tid];
    float4 bv = ((const float4*)b)[tid];
    *(uint32_t*)&g_yf8[(size_t)row*CDIM + tid*4] =
        pack4_e4m3((v.x-mean)*rs*wv.x + bv.x, (v.y-mean)*rs*wv.y + bv.y,
                   (v.z-mean)*rs*wv.z + bv.z, (v.w-mean)*rs*wv.w + bv.w);
}

// ------------------------- q/k per-head LN over D=64 ------------------------
__global__ void k_qkln(const float* __restrict__ qw, const float* __restrict__ qb,
                       const float* __restrict__ kw, const float* __restrict__ kb){
    int gwarp = (blockIdx.x*blockDim.x + threadIdx.x) >> 5;
    int lane  = threadIdx.x & 31;
    const int ROWS = BB*NHEAD*SEQ;
    int tensor = (gwarp >= ROWS) ? 1 : 0;
    int row    = tensor ? gwarp - ROWS : gwarp;
    bf16* buf  = tensor ? g_K : g_Q;
    const float* w = tensor ? kw : qw;
    const float* b = tensor ? kb : qb;
    bf16* p = buf + (size_t)row*HD;
    float x0 = __bfloat162float(p[lane]);
    float x1 = __bfloat162float(p[lane+32]);
    float s  = x0 + x1;
    float sq = x0*x0 + x1*x1;
    #pragma unroll
    for (int o = 16; o; o >>= 1){
        s  += __shfl_xor_sync(0xffffffffu, s,  o);
        sq += __shfl_xor_sync(0xffffffffu, sq, o);
    }
    float mean = s * (1.f/HD);
    float var  = sq * (1.f/HD) - mean*mean;
    float rs   = rsqrtf(var + 1e-5f);
    p[lane]    = __float2bfloat16((x0-mean)*rs*w[lane]    + b[lane]);
    p[lane+32] = __float2bfloat16((x1-mean)*rs*w[lane+32] + b[lane+32]);
}

// =================== FP8 NT GEMM (mma.m16n8k32.e4m3, 128x256) ================
#define GBM 128
#define GBN 256
#define GBK 64
#define LDSB 80                         // bytes per smem row (64 data + 16 pad)
#define STAGE_A (GBM*LDSB)              // 10240
#define STAGE_B (GBN*LDSB)              // 20480
#define GEMM_SMEM (2*(STAGE_A+STAGE_B)) // 61440

__device__ __forceinline__ void cp16(void* s, const void* g){
    unsigned int a = (unsigned int)__cvta_generic_to_shared(s);
    asm volatile("cp.async.cg.shared.global [%0], [%1], 16;\n" :: "r"(a), "l"(g));
}

__device__ __forceinline__ void mma_e4m3(float* c, uint32_t a0, uint32_t a1,
                                         uint32_t a2, uint32_t a3,
                                         uint32_t b0, uint32_t b1){
    asm volatile(
        "mma.sync.aligned.m16n8k32.row.col.f32.e4m3.e4m3.f32 "
        "{%0,%1,%2,%3}, {%4,%5,%6,%7}, {%8,%9}, {%0,%1,%2,%3};"
        : "+f"(c[0]), "+f"(c[1]), "+f"(c[2]), "+f"(c[3])
        : "r"(a0), "r"(a1), "r"(a2), "r"(a3), "r"(b0), "r"(b1));
}

// EPI==1: A=g_yf8, B=g_W1f8, K=1024; bias+gelu -> g_catf8 / qkv -> bf16 (p0=mlp_bias)
// EPI==2: A=g_catf8, B=g_W2f8, K=5120; out = x + lsg*(acc + b2) (p0=x, p1=lsg)
template<int EPI, int KD>
__global__ void __launch_bounds__(256, 1) k_gemm(const float* __restrict__ p0,
                                                 const float* __restrict__ p1,
                                                 float* __restrict__ pout){
    extern __shared__ unsigned char sm[];
    unsigned char* sA = sm;                    // [2][GBM][LDSB]
    unsigned char* sB = sm + 2*STAGE_A;        // [2][GBN][LDSB]
    const uint8_t* A = (EPI == 1) ? g_yf8  : g_catf8;
    const uint8_t* B = (EPI == 1) ? g_W1f8 : g_W2f8;
    const int bx = blockIdx.x, by = blockIdx.y;
    const int tid = threadIdx.x, lane = tid & 31;
    const int warp = tid >> 5, wm = warp >> 2, wn = warp & 3;  // 2x4 warps, 64x64 tiles
    const uint8_t* Ab = A + (size_t)by*GBM*KD;
    const uint8_t* Bb = B + (size_t)bx*GBN*KD;

    float acc[4][8][4];
    #pragma unroll
    for (int i = 0; i < 4; i++)
        #pragma unroll
        for (int j = 0; j < 8; j++)
            #pragma unroll
            for (int e = 0; e < 4; e++) acc[i][j][e] = 0.f;

    const int KT = KD / GBK;
    auto load_stage = [&](int st, int kt){
        int k0 = kt*GBK;
        // A: 128 rows x 64B = 512 chunks of 16B; 2 per thread
        #pragma unroll
        for (int i = 0; i < 2; i++){
            int ch = tid + i*256;
            int r = ch >> 2, s = (ch & 3) * 16;
            cp16(sA + st*STAGE_A + r*LDSB + s, Ab + (size_t)r*KD + k0 + s);
        }
        // B: 256 rows x 64B = 1024 chunks; 4 per thread
        #pragma unroll
        for (int i = 0; i < 4; i++){
            int ch = tid + i*256;
            int r = ch >> 2, s = (ch & 3) * 16;
            cp16(sB + st*STAGE_B + r*LDSB + s, Bb + (size_t)r*KD + k0 + s);
        }
        asm volatile("cp.async.commit_group;\n");
    };

    load_stage(0, 0);
    const int row = lane >> 2, quad = lane & 3;
    for (int kt = 0; kt < KT; kt++){
        if (kt + 1 < KT){
            load_stage((kt+1) & 1, kt+1);
            asm volatile("cp.async.wait_group 1;\n");
        } else {
            asm volatile("cp.async.wait_group 0;\n");
        }
        __syncthreads();
        const unsigned char* pA = sA + (kt & 1)*STAGE_A;
        const unsigned char* pB = sB + (kt & 1)*STAGE_B;
        #pragma unroll
        for (int ks = 0; ks < 2; ks++){
            int kb = ks*32 + quad*4;
            uint32_t a[4][4];
            #pragma unroll
            for (int mt = 0; mt < 4; mt++){
                int r0 = wm*64 + mt*16 + row;
                a[mt][0] = *(const uint32_t*)(pA + r0*LDSB + kb);
                a[mt][1] = *(const uint32_t*)(pA + (r0+8)*LDSB + kb);
                a[mt][2] = *(const uint32_t*)(pA + r0*LDSB + kb + 16);
                a[mt][3] = *(const uint32_t*)(pA + (r0+8)*LDSB + kb + 16);
            }
            #pragma unroll
            for (int nt = 0; nt < 8; nt++){
                int n0 = wn*64 + nt*8 + row;
                uint32_t b0 = *(const uint32_t*)(pB + n0*LDSB + kb);
                uint32_t b1 = *(const uint32_t*)(pB + n0*LDSB + kb + 16);
                #pragma unroll
                for (int mt = 0; mt < 4; mt++)
                    mma_e4m3(acc[mt][nt], a[mt][0], a[mt][1], a[mt][2], a[mt][3], b0, b1);
            }
        }
        __syncthreads();
    }

    // -------- register epilogue: thread owns (row, row+8) x 2 cols per tile --
    #pragma unroll
    for (int mt = 0; mt < 4; mt++){
        #pragma unroll
        for (int nt = 0; nt < 8; nt++){
            int m0 = by*GBM + wm*64 + mt*16 + row;
            int o  = bx*GBN + wn*64 + nt*8 + quad*2;
            #pragma unroll
            for (int half = 0; half < 2; half++){
                int m = m0 + half*8;
                float v0 = acc[mt][nt][half*2 + 0];
                float v1 = acc[mt][nt][half*2 + 1];
                if (EPI == 1){
                    // bias = concat(zeros(3C), mlp_bias) over 7168 outputs
                    if (o >= 3*CDIM){ v0 += p0[o - 3*CDIM]; v1 += p0[o + 1 - 3*CDIM]; }
                    if (o < HID){
                        float g0 = 0.5f*v0*(1.f + erff(v0*0.70710678118654752f));
                        float g1 = 0.5f*v1*(1.f + erff(v1*0.70710678118654752f));
                        uint16_t pk = (uint16_t)f2e4m3(g0) | ((uint16_t)f2e4m3(g1) << 8);
                        *(uint16_t*)&g_catf8[(size_t)m*KCAT + o] = pk;
                    } else {
                        int c2 = o - HID;
                        int reg = c2 >> 10;
                        int cc  = c2 & 1023;
                        int h = cc >> 6, d = cc & 63;
                        int bt = m >> 10, n = m & 1023;
                        bf16* base = (reg == 0) ? g_Q : ((reg == 1) ? g_K : g_V);
                        __nv_bfloat162 hv = __floats2bfloat162_rn(v0, v1);
                        *(__nv_bfloat162*)(base + ((size_t)(bt*NHEAD + h)*SEQ + n)*HD + d) = hv;
                    }
                } else {
                    size_t oi = (size_t)m*CDIM + o;
                    float2 xv = *(const float2*)(p0 + oi);
                    float2 ov;
                    ov.x = xv.x + p1[o]   * (v0 + g_b2[o]);
                    ov.y = xv.y + p1[o+1] * (v1 + g_b2[o+1]);
                    *(float2*)(pout + oi) = ov;
                }
            }
        }
    }
}

// ------------------------- flash attention (64x64 tiles) --------------------
#define LQK 72
#define LSF 68
#define ATTN_SMEM (4*64*LQK*2 + 2*64*LSF*4 + 3*64*4)   // 72448

__global__ void __launch_bounds__(128) k_attn(){
    extern __shared__ char sm_[];
    bf16*  sQ = (bf16*)sm_;
    bf16*  sK = sQ + 64*LQK;
    bf16*  sV = sK + 64*LQK;
    bf16*  sP = sV + 64*LQK;
    float* sS = (float*)(sP + 64*LQK);
    float* sO = sS + 64*LSF;
    float* sM = sO + 64*LSF;
    float* sL = sM + 64;
    float* sAl = sL + 64;

    int bid = blockIdx.x;
    int qt = bid & 15, bh = bid >> 4;
    int tid = threadIdx.x;
    const bf16* Qb = g_Q + (size_t)bh*SEQ*HD;
    const bf16* Kb = g_K + (size_t)bh*SEQ*HD;
    const bf16* Vb = g_V + (size_t)bh*SEQ*HD;

    #pragma unroll
    for (int i = 0; i < 4; i++){
        int ch = tid + i*128;
        int r = ch >> 3, c8 = (ch & 7) * 8;
        *(float4*)&sQ[r*LQK + c8] = *(const float4*)&Qb[(size_t)(qt*64 + r)*HD + c8];
    }
    for (int i = tid; i < 64*LSF; i += 128) sO[i] = 0.f;
    if (tid < 64){ sM[tid] = -1e30f; sL[tid] = 0.f; }
    __syncthreads();

    int w = tid >> 5;
    for (int j = 0; j < 16; j++){
        #pragma unroll
        for (int i = 0; i < 4; i++){
            int ch = tid + i*128;
            int r = ch >> 3, c8 = (ch & 7) * 8;
            *(float4*)&sK[r*LQK + c8] = *(const float4*)&Kb[(size_t)(j*64 + r)*HD + c8];
            *(float4*)&sV[r*LQK + c8] = *(const float4*)&Vb[(size_t)(j*64 + r)*HD + c8];
        }
        __syncthreads();

        { // S = scale * Q @ K^T
            wmma::fragment<wmma::accumulator,16,16,16,float> s[4];
            #pragma unroll
            for (int n = 0; n < 4; n++) wmma::fill_fragment(s[n], 0.f);
            #pragma unroll
            for (int kk = 0; kk < 64; kk += 16){
                wmma::fragment<wmma::matrix_a,16,16,16,bf16,wmma::row_major> a;
                wmma::load_matrix_sync(a, sQ + (w*16)*LQK + kk, LQK);
                #pragma unroll
                for (int n = 0; n < 4; n++){
                    wmma::fragment<wmma::matrix_b,16,16,16,bf16,wmma::col_major> bfr;
                    wmma::load_matrix_sync(bfr, sK + (n*16)*LQK + kk, LQK);
                    wmma::mma_sync(s[n], a, bfr, s[n]);
                }
            }
            #pragma unroll
            for (int n = 0; n < 4; n++){
                #pragma unroll
                for (int e = 0; e < s[n].num_elements; e++) s[n].x[e] *= 0.125f;
                wmma::store_matrix_sync(sS + (w*16)*LSF + n*16, s[n], LSF, wmma::mem_row_major);
            }
        }
        __syncthreads();

        if (tid < 64){  // online softmax row update
            float* sr = sS + tid*LSF;
            float mold = sM[tid];
            float ml = -1e30f;
            #pragma unroll 8
            for (int c = 0; c < 64; c++) ml = fmaxf(ml, sr[c]);
            float mnew  = fmaxf(mold, ml);
            float alpha = __expf(mold - mnew);
            float sum = 0.f;
            bf16* pr = sP + tid*LQK;
            #pragma unroll 8
            for (int c = 0; c < 64; c++){
                float p = __expf(sr[c] - mnew);
                sum += p;
                pr[c] = __float2bfloat16(p);
            }
            sM[tid] = mnew;
            sL[tid] = sL[tid]*alpha + sum;
            sAl[tid] = alpha;
        }
        __syncthreads();

        for (int i = tid; i < 64*64; i += 128){
            int r = i >> 6, c = i & 63;
            sO[r*LSF + c] *= sAl[r];
        }
        __syncthreads();

        { // O += P @ V
            wmma::fragment<wmma::matrix_a,16,16,16,bf16,wmma::row_major> a[4];
            #pragma unroll
            for (int kk = 0; kk < 4; kk++)
                wmma::load_matrix_sync(a[kk], sP + (w*16)*LQK + kk*16, LQK);
            #pragma unroll
            for (int n = 0; n < 4; n++){
                wmma::fragment<wmma::accumulator,16,16,16,float> cf;
                wmma::load_matrix_sync(cf, sO + (w*16)*LSF + n*16, LSF, wmma::mem_row_major);
                #pragma unroll
                for (int kk = 0; kk < 4; kk++){
                    wmma::fragment<wmma::matrix_b,16,16,16,bf16,wmma::row_major> bfr;
                    wmma::load_matrix_sync(bfr, sV + (kk*16)*LQK + n*16, LQK);
                    wmma::mma_sync(cf, a[kk], bfr, cf);
                }
                wmma::store_matrix_sync(sO + (w*16)*LSF + n*16, cf, LSF, wmma::mem_row_major);
            }
        }
        __syncthreads();
    }

    if (tid < 64){
        float inv = 1.f / sL[tid];
        int b = bh >> 4, h = bh & 15;
        int n = qt*64 + tid;
        uint8_t* dst = g_catf8 + (size_t)(b*SEQ + n)*KCAT + HID + h*64;
        #pragma unroll
        for (int c = 0; c < 64; c += 4){
            *(uint32_t*)(dst + c) = pack4_e4m3(
                sO[tid*LSF + c]     * inv, sO[tid*LSF + c + 1] * inv,
                sO[tid*LSF + c + 2] * inv, sO[tid*LSF + c + 3] * inv);
        }
    }
}

// ------------------------- launch --------------------------------------------
extern "C" void kernel_launch(void* const* d_in, const int* in_sizes, int n_in,
                              void* d_out, int out_size){
    (void)in_sizes; (void)n_in; (void)out_size;
    const float* x     = (const float*)d_in[0];
    const float* inw   = (const float*)d_in[1];
    const float* inb   = (const float*)d_in[2];
    const float* w1    = (const float*)d_in[3];
    const float* mbias = (const float*)d_in[4];
    const float* qw    = (const float*)d_in[5];
    const float* qb    = (const float*)d_in[6];
    const float* kw    = (const float*)d_in[7];
    const float* kb    = (const float*)d_in[8];
    const float* w2    = (const float*)d_in[9];
    const float* ob    = (const float*)d_in[10];
    const float* lsg   = (const float*)d_in[11];
    float* out = (float*)d_out;

    cudaFuncSetAttribute(k_gemm<1, CDIM>, cudaFuncAttributeMaxDynamicSharedMemorySize, GEMM_SMEM);
    cudaFuncSetAttribute(k_gemm<2, KCAT>, cudaFuncAttributeMaxDynamicSharedMemorySize, GEMM_SMEM);
    cudaFuncSetAttribute(k_attn,          cudaFuncAttributeMaxDynamicSharedMemorySize, ATTN_SMEM);

    k_convw1<<<(NOUT1*CDIM/4)/256, 256>>>(w1);
    k_convw2<<<(CDIM*KCAT/4)/256, 256>>>(w2);
    k_b2<<<4, 256>>>(ob);
    k_ln1<<<MTOK, 256>>>(x, inw, inb);

    dim3 g1(NOUT1/GBN, MTOK/GBM);          // (28, 64)
    k_gemm<1, CDIM><<<g1, 256, GEMM_SMEM>>>(mbias, nullptr, nullptr);

    k_qkln<<<(2*BB*NHEAD*SEQ)/8, 256>>>(qw, qb, kw, kb);

    k_attn<<<BB*NHEAD*(SEQ/64), 128, ATTN_SMEM>>>();

    dim3 g2(CDIM/GBN, MTOK/GBM);           // (4, 64)
    k_gemm<2, KCAT><<<g2, 256, GEMM_SMEM>>>(x, lsg, out);
}

// round 17
// speedup vs baseline: 1.4887x; 1.3817x over previous
#include <cuda_runtime.h>
#include <cuda_bf16.h>
#include <cuda_fp8.h>
#include <cstdint>

typedef __nv_bfloat16 bf16;

#define BB    8
#define SEQ   1024
#define CDIM  1024
#define NHEAD 16
#define HD    64
#define HID   4096
#define MTOK  (BB*SEQ)           // 8192
#define NOUT1 (HID + 3*CDIM)     // 7168
#define KCAT  (HID + CDIM)       // 5120

// ------------------------- scratch (static device globals) ------------------
__device__ uint8_t g_yf8 [(size_t)MTOK*CDIM];    // LN(x) e4m3
__device__ uint8_t g_W1f8[(size_t)NOUT1*CDIM];   // in_proj_w e4m3
__device__ uint8_t g_W2f8[(size_t)CDIM*KCAT];    // folded out_proj_w e4m3
__device__ float   g_b2  [CDIM];                 // folded out_proj_b
__device__ uint8_t g_catf8[(size_t)MTOK*KCAT];   // [gelu(mlp) | x_attn] e4m3
__device__ bf16    g_Q  [(size_t)MTOK*CDIM];     // [B,H,N,D] bf16 (pre-scaled 1/8)
__device__ bf16    g_K  [(size_t)MTOK*CDIM];     // [B,H,N,D]
__device__ bf16    g_V  [(size_t)MTOK*CDIM];     // [B,H,D,N]  (TRANSPOSED)

__device__ __forceinline__ uint8_t f2e4m3(float f){
    return (uint8_t)__nv_cvt_float_to_fp8(f, __NV_SATFINITE, __NV_E4M3);
}
__device__ __forceinline__ uint32_t pack4_e4m3(float a, float b, float c, float d){
    return (uint32_t)f2e4m3(a) | ((uint32_t)f2e4m3(b) << 8) |
           ((uint32_t)f2e4m3(c) << 16) | ((uint32_t)f2e4m3(d) << 24);
}
__device__ __forceinline__ uint32_t packbf2(float lo, float hi){
    __nv_bfloat162 h = __floats2bfloat162_rn(lo, hi);
    return *(uint32_t*)&h;
}
__device__ __forceinline__ void cp16(void* s, const void* g){
    unsigned int a = (unsigned int)__cvta_generic_to_shared(s);
    asm volatile("cp.async.cg.shared.global [%0], [%1], 16;\n" :: "r"(a), "l"(g));
}

// ------------------------- weight conversion kernels ------------------------
__global__ void k_convw1(const float* __restrict__ w){
    size_t idx = ((size_t)blockIdx.x*blockDim.x + threadIdx.x)*4;
    float4 v = *(const float4*)(w + idx);
    *(uint32_t*)&g_W1f8[idx] = pack4_e4m3(v.x, v.y, v.z, v.w);
}

__global__ void k_convw2(const float* __restrict__ w){
    size_t idx = ((size_t)blockIdx.x*blockDim.x + threadIdx.x)*4;
    float4 a = *(const float4*)(w + idx);
    float4 b = *(const float4*)(w + (size_t)CDIM*KCAT + idx);
    *(uint32_t*)&g_W2f8[idx] = pack4_e4m3(a.x+b.x, a.y+b.y, a.z+b.z, a.w+b.w);
}

__global__ void k_b2(const float* __restrict__ ob){
    int c = blockIdx.x*blockDim.x + threadIdx.x;
    if (c < CDIM) g_b2[c] = ob[c] + ob[CDIM + c];
}

// ------------------------- LN over C=1024 (input) ----------------------------
__global__ void k_ln1(const float* __restrict__ x,
                      const float* __restrict__ w,
                      const float* __restrict__ b){
    int row = blockIdx.x;
    int tid = threadIdx.x;
    const float* xr = x + (size_t)row*CDIM;
    float4 v = ((const float4*)xr)[tid];
    float s  = v.x + v.y + v.z + v.w;
    float sq = v.x*v.x + v.y*v.y + v.z*v.z + v.w*v.w;
    #pragma unroll
    for (int o = 16; o; o >>= 1){
        s  += __shfl_xor_sync(0xffffffffu, s,  o);
        sq += __shfl_xor_sync(0xffffffffu, sq, o);
    }
    __shared__ float ss[8], ssq[8];
    __shared__ float smean, srstd;
    int wp = tid >> 5, ln = tid & 31;
    if (ln == 0){ ss[wp] = s; ssq[wp] = sq; }
    __syncthreads();
    if (tid == 0){
        float S = 0.f, Q = 0.f;
        #pragma unroll
        for (int i = 0; i < 8; i++){ S += ss[i]; Q += ssq[i]; }
        float mean = S * (1.f/CDIM);
        float var  = Q * (1.f/CDIM) - mean*mean;
        smean = mean; srstd = rsqrtf(var + 1e-5f);
    }
    __syncthreads();
    float mean = smean, rs = srstd;
    float4 wv = ((const float4*)w)[tid];
    float4 bv = ((const float4*)b)[tid];
    *(uint32_t*)&g_yf8[(size_t)row*CDIM + tid*4] =
        pack4_e4m3((v.x-mean)*rs*wv.x + bv.x, (v.y-mean)*rs*wv.y + bv.y,
                   (v.z-mean)*rs*wv.z + bv.z, (v.w-mean)*rs*wv.w + bv.w);
}

// --------------- q/k per-head LN over D=64 (q scaled by 1/8) ----------------
__global__ void k_qkln(const float* __restrict__ qw, const float* __restrict__ qb,
                       const float* __restrict__ kw, const float* __restrict__ kb){
    int gwarp = (blockIdx.x*blockDim.x + threadIdx.x) >> 5;
    int lane  = threadIdx.x & 31;
    const int ROWS = BB*NHEAD*SEQ;
    int tensor = (gwarp >= ROWS) ? 1 : 0;
    int row    = tensor ? gwarp - ROWS : gwarp;
    bf16* buf  = tensor ? g_K : g_Q;
    const float* w = tensor ? kw : qw;
    const float* b = tensor ? kb : qb;
    float sc = tensor ? 1.f : 0.125f;    // fold 1/sqrt(D) into q
    bf16* p = buf + (size_t)row*HD;
    float x0 = __bfloat162float(p[lane]);
    float x1 = __bfloat162float(p[lane+32]);
    float s  = x0 + x1;
    float sq = x0*x0 + x1*x1;
    #pragma unroll
    for (int o = 16; o; o >>= 1){
        s  += __shfl_xor_sync(0xffffffffu, s,  o);
        sq += __shfl_xor_sync(0xffffffffu, sq, o);
    }
    float mean = s * (1.f/HD);
    float var  = sq * (1.f/HD) - mean*mean;
    float rs   = rsqrtf(var + 1e-5f);
    p[lane]    = __float2bfloat16(((x0-mean)*rs*w[lane]    + b[lane])    * sc);
    p[lane+32] = __float2bfloat16(((x1-mean)*rs*w[lane+32] + b[lane+32]) * sc);
}

// =================== FP8 NT GEMM (mma.m16n8k32.e4m3, 128x256) ================
#define GBM 128
#define GBN 256
#define GBK 64
#define LDSB 80
#define STAGE_A (GBM*LDSB)
#define STAGE_B (GBN*LDSB)
#define GEMM_SMEM (2*(STAGE_A+STAGE_B))   // 61440

__device__ __forceinline__ void mma_e4m3(float* c, uint32_t a0, uint32_t a1,
                                         uint32_t a2, uint32_t a3,
                                         uint32_t b0, uint32_t b1){
    asm volatile(
        "mma.sync.aligned.m16n8k32.row.col.f32.e4m3.e4m3.f32 "
        "{%0,%1,%2,%3}, {%4,%5,%6,%7}, {%8,%9}, {%0,%1,%2,%3};"
        : "+f"(c[0]), "+f"(c[1]), "+f"(c[2]), "+f"(c[3])
        : "r"(a0), "r"(a1), "r"(a2), "r"(a3), "r"(b0), "r"(b1));
}

// EPI==1: A=g_yf8, B=g_W1f8, K=1024; bias+gelu -> g_catf8 / qkv scatter (V transposed)
// EPI==2: A=g_catf8, B=g_W2f8, K=5120; out = x + lsg*(acc + b2)
template<int EPI, int KD>
__global__ void __launch_bounds__(256, 1) k_gemm(const float* __restrict__ p0,
                                                 const float* __restrict__ p1,
                                                 float* __restrict__ pout){
    extern __shared__ unsigned char sm[];
    unsigned char* sA = sm;
    unsigned char* sB = sm + 2*STAGE_A;
    const uint8_t* A = (EPI == 1) ? g_yf8  : g_catf8;
    const uint8_t* B = (EPI == 1) ? g_W1f8 : g_W2f8;
    const int bx = blockIdx.x, by = blockIdx.y;
    const int tid = threadIdx.x, lane = tid & 31;
    const int warp = tid >> 5, wm = warp >> 2, wn = warp & 3;
    const uint8_t* Ab = A + (size_t)by*GBM*KD;
    const uint8_t* Bb = B + (size_t)bx*GBN*KD;

    float acc[4][8][4];
    #pragma unroll
    for (int i = 0; i < 4; i++)
        #pragma unroll
        for (int j = 0; j < 8; j++)
            #pragma unroll
            for (int e = 0; e < 4; e++) acc[i][j][e] = 0.f;

    const int KT = KD / GBK;
    auto load_stage = [&](int st, int kt){
        int k0 = kt*GBK;
        #pragma unroll
        for (int i = 0; i < 2; i++){
            int ch = tid + i*256;
            int r = ch >> 2, s = (ch & 3) * 16;
            cp16(sA + st*STAGE_A + r*LDSB + s, Ab + (size_t)r*KD + k0 + s);
        }
        #pragma unroll
        for (int i = 0; i < 4; i++){
            int ch = tid + i*256;
            int r = ch >> 2, s = (ch & 3) * 16;
            cp16(sB + st*STAGE_B + r*LDSB + s, Bb + (size_t)r*KD + k0 + s);
        }
        asm volatile("cp.async.commit_group;\n");
    };

    load_stage(0, 0);
    const int row = lane >> 2, quad = lane & 3;
    for (int kt = 0; kt < KT; kt++){
        if (kt + 1 < KT){
            load_stage((kt+1) & 1, kt+1);
            asm volatile("cp.async.wait_group 1;\n");
        } else {
            asm volatile("cp.async.wait_group 0;\n");
        }
        __syncthreads();
        const unsigned char* pA = sA + (kt & 1)*STAGE_A;
        const unsigned char* pB = sB + (kt & 1)*STAGE_B;
        #pragma unroll
        for (int ks = 0; ks < 2; ks++){
            int kb = ks*32 + quad*4;
            uint32_t a[4][4];
            #pragma unroll
            for (int mt = 0; mt < 4; mt++){
                int r0 = wm*64 + mt*16 + row;
                a[mt][0] = *(const uint32_t*)(pA + r0*LDSB + kb);
                a[mt][1] = *(const uint32_t*)(pA + (r0+8)*LDSB + kb);
                a[mt][2] = *(const uint32_t*)(pA + r0*LDSB + kb + 16);
                a[mt][3] = *(const uint32_t*)(pA + (r0+8)*LDSB + kb + 16);
            }
            #pragma unroll
            for (int nt = 0; nt < 8; nt++){
                int n0 = wn*64 + nt*8 + row;
                uint32_t b0 = *(const uint32_t*)(pB + n0*LDSB + kb);
                uint32_t b1 = *(const uint32_t*)(pB + n0*LDSB + kb + 16);
                #pragma unroll
                for (int mt = 0; mt < 4; mt++)
                    mma_e4m3(acc[mt][nt], a[mt][0], a[mt][1], a[mt][2], a[mt][3], b0, b1);
            }
        }
        __syncthreads();
    }

    #pragma unroll
    for (int mt = 0; mt < 4; mt++){
        #pragma unroll
        for (int nt = 0; nt < 8; nt++){
            int m0 = by*GBM + wm*64 + mt*16 + row;
            int o  = bx*GBN + wn*64 + nt*8 + quad*2;
            #pragma unroll
            for (int half = 0; half < 2; half++){
                int m = m0 + half*8;
                float v0 = acc[mt][nt][half*2 + 0];
                float v1 = acc[mt][nt][half*2 + 1];
                if (EPI == 1){
                    if (o >= 3*CDIM){ v0 += p0[o - 3*CDIM]; v1 += p0[o + 1 - 3*CDIM]; }
                    if (o < HID){
                        float g0 = 0.5f*v0*(1.f + erff(v0*0.70710678118654752f));
                        float g1 = 0.5f*v1*(1.f + erff(v1*0.70710678118654752f));
                        uint16_t pk = (uint16_t)f2e4m3(g0) | ((uint16_t)f2e4m3(g1) << 8);
                        *(uint16_t*)&g_catf8[(size_t)m*KCAT + o] = pk;
                    } else {
                        int c2 = o - HID;
                        int reg = c2 >> 10;
                        int cc  = c2 & 1023;
                        int h = cc >> 6, d = cc & 63;
                        int bt = m >> 10, n = m & 1023;
                        if (reg == 2){
                            // V transposed: [B,H,D,N]
                            size_t offT = ((size_t)(bt*NHEAD + h)*HD + d)*SEQ + n;
                            g_V[offT]       = __float2bfloat16(v0);
                            g_V[offT + SEQ] = __float2bfloat16(v1);
                        } else {
                            bf16* base = (reg == 0) ? g_Q : g_K;
                            __nv_bfloat162 hv = __floats2bfloat162_rn(v0, v1);
                            *(__nv_bfloat162*)(base + ((size_t)(bt*NHEAD + h)*SEQ + n)*HD + d) = hv;
                        }
                    }
                } else {
                    size_t oi = (size_t)m*CDIM + o;
                    float2 xv = *(const float2*)(p0 + oi);
                    float2 ov;
                    ov.x = xv.x + p1[o]   * (v0 + g_b2[o]);
                    ov.y = xv.y + p1[o+1] * (v1 + g_b2[o+1]);
                    *(float2*)(pout + oi) = ov;
                }
            }
        }
    }
}

// ================= flash attention v2 (register softmax, mma) ================
#define BRQ 128
#define BCK 64
#define LDK 72                                   // halves per smem row
#define ATTN_SMEM ((BRQ*LDK + 4*BCK*LDK)*2)      // 55296 bytes

__device__ __forceinline__ void mma_bf16(float* c, uint32_t a0, uint32_t a1,
                                         uint32_t a2, uint32_t a3,
                                         uint32_t b0, uint32_t b1){
    asm volatile(
        "mma.sync.aligned.m16n8k16.row.col.f32.bf16.bf16.f32 "
        "{%0,%1,%2,%3}, {%4,%5,%6,%7}, {%8,%9}, {%0,%1,%2,%3};"
        : "+f"(c[0]), "+f"(c[1]), "+f"(c[2]), "+f"(c[3])
        : "r"(a0), "r"(a1), "r"(a2), "r"(a3), "r"(b0), "r"(b1));
}

__global__ void __launch_bounds__(256, 2) k_attn(){
    extern __shared__ bf16 sm_[];
    bf16* sQ = sm_;                        // [128][72]
    bf16* sK = sm_ + BRQ*LDK;              // 2 stages x [64][72]
    bf16* sV = sK + 2*BCK*LDK;             // 2 stages x [64][72] (V^T: rows=d)

    const int qt = blockIdx.x, bh = blockIdx.y;
    const int tid = threadIdx.x, warp = tid >> 5, lane = tid & 31;
    const int rw = lane >> 2, q2 = (lane & 3) * 2;
    const bf16* Qg = g_Q + ((size_t)bh*SEQ + qt*BRQ)*HD;
    const bf16* Kg = g_K + (size_t)bh*SEQ*HD;
    const bf16* Vg = g_V + (size_t)bh*HD*SEQ;

    // Q tile: 128 rows x 128B = 1024 chunks of 16B
    #pragma unroll
    for (int i = 0; i < 4; i++){
        int ch = tid + i*256;
        int r = ch >> 3, c = (ch & 7) * 8;
        cp16(&sQ[r*LDK + c], Qg + (size_t)r*HD + c);
    }
    asm volatile("cp.async.commit_group;\n");

    auto loadKV = [&](int j, int st){
        int kv0 = j*BCK;
        #pragma unroll
        for (int i = 0; i < 2; i++){
            int ch = tid + i*256;
            int r = ch >> 3, c = (ch & 7) * 8;
            cp16(&sK[st*BCK*LDK + r*LDK + c], Kg + (size_t)(kv0 + r)*HD + c);
        }
        #pragma unroll
        for (int i = 0; i < 2; i++){
            int ch = tid + i*256;
            int r = ch >> 3, c = (ch & 7) * 8;   // r = d-row, c = kv offset
            cp16(&sV[st*BCK*LDK + r*LDK + c], Vg + (size_t)r*SEQ + kv0 + c);
        }
        asm volatile("cp.async.commit_group;\n");
    };

    loadKV(0, 0);
    loadKV(1, 1);

    uint32_t aq[4][4];
    float o[8][4];
    #pragma unroll
    for (int dt = 0; dt < 8; dt++)
        #pragma unroll
        for (int e = 0; e < 4; e++) o[dt][e] = 0.f;
    float m0 = -1e30f, m1 = -1e30f, l0 = 0.f, l1 = 0.f;

    const int NJ = SEQ / BCK;   // 16
    for (int j = 0; j < NJ; j++){
        int st = j & 1;
        if (j + 1 < NJ) asm volatile("cp.async.wait_group 1;\n");
        else            asm volatile("cp.async.wait_group 0;\n");
        __syncthreads();
        if (j == 0){
            #pragma unroll
            for (int ks = 0; ks < 4; ks++){
                const bf16* qb_ = &sQ[(warp*16 + rw)*LDK + ks*16 + q2];
                aq[ks][0] = *(const uint32_t*)qb_;
                aq[ks][1] = *(const uint32_t*)(qb_ + 8*LDK);
                aq[ks][2] = *(const uint32_t*)(qb_ + 8);
                aq[ks][3] = *(const uint32_t*)(qb_ + 8*LDK + 8);
            }
        }
        const bf16* pK = sK + st*BCK*LDK;
        const bf16* pV = sV + st*BCK*LDK;

        // ---- S = Q @ K^T  (16 x 64 per warp, registers) ----
        float s[8][4];
        #pragma unroll
        for (int n8 = 0; n8 < 8; n8++){
            s[n8][0] = s[n8][1] = s[n8][2] = s[n8][3] = 0.f;
            const bf16* kb_ = &pK[(n8*8 + rw)*LDK + q2];
            #pragma unroll
            for (int ks = 0; ks < 4; ks++){
                uint32_t b0 = *(const uint32_t*)(kb_ + ks*16);
                uint32_t b1 = *(const uint32_t*)(kb_ + ks*16 + 8);
                mma_bf16(s[n8], aq[ks][0], aq[ks][1], aq[ks][2], aq[ks][3], b0, b1);
            }
        }

        // ---- online softmax (registers + quad shuffles) ----
        float mx0 = -1e30f, mx1 = -1e30f;
        #pragma unroll
        for (int n8 = 0; n8 < 8; n8++){
            mx0 = fmaxf(mx0, fmaxf(s[n8][0], s[n8][1]));
            mx1 = fmaxf(mx1, fmaxf(s[n8][2], s[n8][3]));
        }
        mx0 = fmaxf(mx0, __shfl_xor_sync(0xffffffffu, mx0, 1));
        mx0 = fmaxf(mx0, __shfl_xor_sync(0xffffffffu, mx0, 2));
        mx1 = fmaxf(mx1, __shfl_xor_sync(0xffffffffu, mx1, 1));
        mx1 = fmaxf(mx1, __shfl_xor_sync(0xffffffffu, mx1, 2));
        float mn0 = fmaxf(m0, mx0), mn1 = fmaxf(m1, mx1);
        float al0 = __expf(m0 - mn0), al1 = __expf(m1 - mn1);
        m0 = mn0; m1 = mn1;
        float ls0 = 0.f, ls1 = 0.f;
        #pragma unroll
        for (int n8 = 0; n8 < 8; n8++){
            float p0 = __expf(s[n8][0] - mn0);
            float p1 = __expf(s[n8][1] - mn0);
            float p2 = __expf(s[n8][2] - mn1);
            float p3 = __expf(s[n8][3] - mn1);
            ls0 += p0 + p1; ls1 += p2 + p3;
            s[n8][0] = p0; s[n8][1] = p1; s[n8][2] = p2; s[n8][3] = p3;
        }
        ls0 += __shfl_xor_sync(0xffffffffu, ls0, 1);
        ls0 += __shfl_xor_sync(0xffffffffu, ls0, 2);
        ls1 += __shfl_xor_sync(0xffffffffu, ls1, 1);
        ls1 += __shfl_xor_sync(0xffffffffu, ls1, 2);
        l0 = l0*al0 + ls0;
        l1 = l1*al1 + ls1;
        #pragma unroll
        for (int dt = 0; dt < 8; dt++){
            o[dt][0] *= al0; o[dt][1] *= al0;
            o[dt][2] *= al1; o[dt][3] *= al1;
        }

        // ---- P (bf16 A-fragments) from S accumulators ----
        uint32_t pa[4][4];
        #pragma unroll
        for (int ks = 0; ks < 4; ks++){
            pa[ks][0] = packbf2(s[2*ks][0],   s[2*ks][1]);
            pa[ks][1] = packbf2(s[2*ks][2],   s[2*ks][3]);
            pa[ks][2] = packbf2(s[2*ks+1][0], s[2*ks+1][1]);
            pa[ks][3] = packbf2(s[2*ks+1][2], s[2*ks+1][3]);
        }

        // ---- O += P @ V  (V^T in smem: rows = d) ----
        #pragma unroll
        for (int dt = 0; dt < 8; dt++){
            const bf16* vb_ = &pV[(dt*8 + rw)*LDK + q2];
            #pragma unroll
            for (int ks = 0; ks < 4; ks++){
                uint32_t b0 = *(const uint32_t*)(vb_ + ks*16);
                uint32_t b1 = *(const uint32_t*)(vb_ + ks*16 + 8);
                mma_bf16(o[dt], pa[ks][0], pa[ks][1], pa[ks][2], pa[ks][3], b0, b1);
            }
        }

        __syncthreads();
        if (j + 2 < NJ) loadKV(j + 2, st);
    }

    // ---- normalize + write fp8 into g_cat ----
    float rl0 = 1.f / l0, rl1 = 1.f / l1;
    int b = bh >> 4, h = bh & 15;
    int tok0 = qt*BRQ + warp*16 + rw;
    uint8_t* d0 = g_catf8 + (size_t)(b*SEQ + tok0)*KCAT + HID + h*64;
    uint8_t* d1 = d0 + (size_t)8*KCAT;
    #pragma unroll
    for (int dt = 0; dt < 8; dt++){
        uint16_t w0 = (uint16_t)f2e4m3(o[dt][0]*rl0) | ((uint16_t)f2e4m3(o[dt][1]*rl0) << 8);
        uint16_t w1 = (uint16_t)f2e4m3(o[dt][2]*rl1) | ((uint16_t)f2e4m3(o[dt][3]*rl1) << 8);
        *(uint16_t*)(d0 + dt*8 + q2) = w0;
        *(uint16_t*)(d1 + dt*8 + q2) = w1;
    }
}

// ------------------------- launch --------------------------------------------
extern "C" void kernel_launch(void* const* d_in, const int* in_sizes, int n_in,
                              void* d_out, int out_size){
    (void)in_sizes; (void)n_in; (void)out_size;
    const float* x     = (const float*)d_in[0];
    const float* inw   = (const float*)d_in[1];
    const float* inb   = (const float*)d_in[2];
    const float* w1    = (const float*)d_in[3];
    const float* mbias = (const float*)d_in[4];
    const float* qw    = (const float*)d_in[5];
    const float* qb    = (const float*)d_in[6];
    const float* kw    = (const float*)d_in[7];
    const float* kb    = (const float*)d_in[8];
    const float* w2    = (const float*)d_in[9];
    const float* ob    = (const float*)d_in[10];
    const float* lsg   = (const float*)d_in[11];
    float* out = (float*)d_out;

    cudaFuncSetAttribute(k_gemm<1, CDIM>, cudaFuncAttributeMaxDynamicSharedMemorySize, GEMM_SMEM);
    cudaFuncSetAttribute(k_gemm<2, KCAT>, cudaFuncAttributeMaxDynamicSharedMemorySize, GEMM_SMEM);
    cudaFuncSetAttribute(k_attn,          cudaFuncAttributeMaxDynamicSharedMemorySize, ATTN_SMEM);

    k_convw1<<<(NOUT1*CDIM/4)/256, 256>>>(w1);
    k_convw2<<<(CDIM*KCAT/4)/256, 256>>>(w2);
    k_b2<<<4, 256>>>(ob);
    k_ln1<<<MTOK, 256>>>(x, inw, inb);

    dim3 g1(NOUT1/GBN, MTOK/GBM);          // (28, 64)
    k_gemm<1, CDIM><<<g1, 256, GEMM_SMEM>>>(mbias, nullptr, nullptr);

    k_qkln<<<(2*BB*NHEAD*SEQ)/8, 256>>>(qw, qb, kw, kb);

    dim3 ga(SEQ/BRQ, BB*NHEAD);            // (8, 128)
    k_attn<<<ga, 256, ATTN_SMEM>>>();

    dim3 g2(CDIM/GBN, MTOK/GBM);           // (4, 64)
    k_gemm<2, KCAT><<<g2, 256, GEMM_SMEM>>>(x, lsg, out);
}